// round 5
// baseline (speedup 1.0000x reference)
#include <cuda_runtime.h>

#define HH 224
#define WW 224
#define STEPS 32
#define NWARP 8
#define ROWS_PER_STRIP 15   // 15 strips * 15 rows = 225 vertex rows
#define STRIPS 15
#define BLOCKS_PER_IMG 15   // 120 warps / 8 warps-per-block

// bucket index: smallest k with value <= t_k, t_k = -2 + 4k/31; 63 = "never counts"
__device__ __forceinline__ int bucketf(float v) {
    float r = fmaf(v, 7.75f, 15.5f);      // (v + 2) * 31/4
    int k = __float2int_ru(r);            // inf -> INT_MAX
    k = max(k, 0);
    k = min(k, 63);
    return k;
}

__global__ __launch_bounds__(256) void ecc_kernel(const float* __restrict__ x,
                                                  float* __restrict__ out) {
    __shared__ int hist[NWARP * 32];
    const int tid = threadIdx.x;
    hist[tid] = 0;
    __syncthreads();

    const int img  = blockIdx.y;
    const float* p = x + (size_t)img * (HH * WW);
    const int warp = tid >> 5;
    const int lane = tid & 31;
    const int wl   = blockIdx.x * NWARP + warp;  // 0..119
    const int cg   = wl & 7;                     // column group 0..7
    const int strip = wl >> 3;                   // 0..14
    const int j    = cg * 32 + lane;             // vertex column (0..255; >=225 inert)
    const int i0   = strip * ROWS_PER_STRIP;

    int* h = hist + warp * 32;

    auto pixb = [&](int r, int c) -> int {
        if (r >= 0 && r < HH && c >= 0 && c < WW)
            return bucketf(__ldg(p + r * WW + c));
        return 63;
    };

    // buckets of pixel row i0-1 at columns j and j-1
    int b_up = pixb(i0 - 1, j);
    int b_ul = __shfl_up_sync(0xffffffffu, b_up, 1);
    if (lane == 0) b_ul = pixb(i0 - 1, j - 1);

#pragma unroll
    for (int r = 0; r < ROWS_PER_STRIP; r++) {
        const int i = i0 + r;
        int b_cur = pixb(i, j);
        int b_l = __shfl_up_sync(0xffffffffu, b_cur, 1);
        if (lane == 0) b_l = pixb(i, j - 1);

        // cell buckets via integer mins (monotone bucketing)
        const int eh  = min(b_up, b_cur);   // horizontal edge (i,j)
        const int ev  = min(b_l,  b_cur);   // vertical edge (i,j)
        const int emn = min(eh, ev);
        const int emx = max(eh, ev);
        const int kv  = min(emn, b_ul);     // vertex (i,j)
        const int kf  = b_cur;              // face (i,j)

        // delta histogram: +1@kv, -1@emn, -1@emx, +1@kf, with cancellation
        if (kv != emn) {
            if (kv  < 32) atomicAdd(&h[kv],  1);
            if (emn < 32) atomicAdd(&h[emn], -1);
        }
        if (emx != kf) {
            if (emx < 32) atomicAdd(&h[emx], -1);
            if (kf  < 32) atomicAdd(&h[kf],  1);
        }
        b_up = b_cur;
        b_ul = b_l;
    }

    __syncthreads();
    // reduce warp replicas, prefix-scan delta -> cumulative ECC, flush to gmem
    if (tid < 32) {
        int v = 0;
#pragma unroll
        for (int w = 0; w < NWARP; w++) v += hist[w * 32 + tid];
#pragma unroll
        for (int d = 1; d < 32; d <<= 1) {
            int n = __shfl_up_sync(0xffffffffu, v, d);
            if (tid >= d) v += n;
        }
        atomicAdd(out + img * 32 + tid, (float)v);
    }
}

extern "C" void kernel_launch(void* const* d_in, const int* in_sizes, int n_in,
                              void* d_out, int out_size) {
    const float* x = (const float*)d_in[0];
    float* out = (float*)d_out;
    const int imgs = in_sizes[0] / (HH * WW);   // 8*3 = 24

    cudaMemsetAsync(out, 0, (size_t)out_size * sizeof(float), 0);
    dim3 grid(BLOCKS_PER_IMG, imgs);
    ecc_kernel<<<grid, 256>>>(x, out);
}

// round 6
// speedup vs baseline: 1.2050x; 1.2050x over previous
#include <cuda_runtime.h>

#define HH 224
#define WW 224
#define STEPS 32
#define NWARP 8
#define RPS 5               // vertex rows per strip: 45 strips * 5 = 225 rows
#define BLOCKS_PER_IMG 45   // 45 strips * 8 col-groups / 8 warps-per-block

// bucket index: smallest k with value <= t_k, t_k = -2 + 4k/31; 63 = "never counts"
__device__ __forceinline__ int bucketf(float v) {
    float r = fmaf(v, 7.75f, 15.5f);      // (v + 2) * 31/4
    int k = __float2int_ru(r);            // inf -> INT_MAX
    k = max(k, 0);
    k = min(k, 63);
    return k;
}

__global__ __launch_bounds__(256) void ecc_kernel(const float* __restrict__ x,
                                                  float* __restrict__ out) {
    __shared__ int hist[NWARP * 32];
    const int tid = threadIdx.x;
    hist[tid] = 0;
    __syncthreads();

    const int img  = blockIdx.y;
    const float* p = x + (size_t)img * (HH * WW);
    const int warp = tid >> 5;
    const int lane = tid & 31;
    const int wl   = blockIdx.x * NWARP + warp;  // 0..359
    const int cg   = wl & 7;                     // column group 0..7
    const int strip = wl >> 3;                   // 0..44
    const int j    = cg * 32 + lane;             // vertex column (0..255; >=225 inert)
    const int i0   = strip * RPS;

    int* h = hist + warp * 32;

    auto pixb = [&](int r, int c) -> int {
        if (r >= 0 && r < HH && c >= 0 && c < WW)
            return bucketf(__ldg(p + r * WW + c));
        return 63;
    };

    // Batch-load all RPS+1 pixel rows (i0-1 .. i0+RPS-1) for column j -> MLP=6
    int b[RPS + 1];
#pragma unroll
    for (int r = 0; r <= RPS; r++) b[r] = pixb(i0 - 1 + r, j);

    // Left-neighbor buckets via shuffle; lane 0 loads column j-1 itself
    int bl[RPS + 1];
#pragma unroll
    for (int r = 0; r <= RPS; r++) {
        bl[r] = __shfl_up_sync(0xffffffffu, b[r], 1);
        if (lane == 0) bl[r] = pixb(i0 - 1 + r, j - 1);
    }

#pragma unroll
    for (int r = 1; r <= RPS; r++) {
        const int b_up = b[r - 1];   // pixel (i-1, j)
        const int b_ul = bl[r - 1];  // pixel (i-1, j-1)
        const int b_cur = b[r];      // pixel (i, j)
        const int b_l  = bl[r];      // pixel (i, j-1)

        // cell buckets via integer mins (monotone bucketing)
        const int eh  = min(b_up, b_cur);   // horizontal edge
        const int ev  = min(b_l,  b_cur);   // vertical edge
        const int emn = min(eh, ev);
        const int emx = max(eh, ev);
        const int kv  = min(emn, b_ul);     // vertex
        const int kf  = b_cur;              // face

        // delta histogram: +1@kv, -1@emn, -1@emx, +1@kf, with cancellation
        if (kv != emn) {
            if (kv  < 32) atomicAdd(&h[kv],  1);
            if (emn < 32) atomicAdd(&h[emn], -1);
        }
        if (emx != kf) {
            if (emx < 32) atomicAdd(&h[emx], -1);
            if (kf  < 32) atomicAdd(&h[kf],  1);
        }
    }

    __syncthreads();
    // reduce warp replicas, prefix-scan delta -> cumulative ECC, flush to gmem
    if (tid < 32) {
        int v = 0;
#pragma unroll
        for (int w = 0; w < NWARP; w++) v += hist[w * 32 + tid];
#pragma unroll
        for (int d = 1; d < 32; d <<= 1) {
            int n = __shfl_up_sync(0xffffffffu, v, d);
            if (tid >= d) v += n;
        }
        atomicAdd(out + img * 32 + tid, (float)v);
    }
}

extern "C" void kernel_launch(void* const* d_in, const int* in_sizes, int n_in,
                              void* d_out, int out_size) {
    const float* x = (const float*)d_in[0];
    float* out = (float*)d_out;
    const int imgs = in_sizes[0] / (HH * WW);   // 8*3 = 24

    cudaMemsetAsync(out, 0, (size_t)out_size * sizeof(float), 0);
    dim3 grid(BLOCKS_PER_IMG, imgs);
    ecc_kernel<<<grid, 256>>>(x, out);
}